// round 4
// baseline (speedup 1.0000x reference)
#include <cuda_runtime.h>

// FiniteWindowTopologicalAttention — fp32 baseline
//   K1: qkv = x @ w_qkv            (SGEMM 262144 x 768 x 256, FFMA2)
//   K2: windowed attention          (16x16 per head, smem-resident)
//   K3: out = ao @ w_proj + b_proj  (SGEMM 262144 x 256 x 256, FFMA2)

#define D_MODEL 256
#define NQKV    768
#define M_TOK   262144          // 4 * 256 * 256
#define NWIN    16384           // 4 * 64 * 64

// scratch (allocation-free rule: __device__ globals)
__device__ float g_qkv[(size_t)M_TOK * NQKV];   // 768 MB
__device__ float g_ao [(size_t)M_TOK * D_MODEL];// 256 MB

// ---------------- packed fp32x2 helpers (sm_103a dual-rate fp32) -------------
__device__ __forceinline__ unsigned long long pack2(float x, float y) {
    unsigned long long r;
    asm("mov.b64 %0, {%1, %2};" : "=l"(r) : "f"(x), "f"(y));
    return r;
}
__device__ __forceinline__ void unpack2(unsigned long long v, float &x, float &y) {
    asm("mov.b64 {%0, %1}, %2;" : "=f"(x), "=f"(y) : "l"(v));
}
__device__ __forceinline__ void ffma2(unsigned long long &c,
                                      unsigned long long a,
                                      unsigned long long b) {
    asm("fma.rn.f32x2 %0, %1, %2, %0;" : "+l"(c) : "l"(a), "l"(b));
}

// ---------------- SGEMM: C[M,N] = A[M,256] * B[256,N] (+bias) ----------------
// BM=128, BN=128, BK=16, 256 threads, 8x8 per thread (as 8x4 f32x2 pairs)
template<int N>
__global__ __launch_bounds__(256, 2)
void sgemm_kernel(const float* __restrict__ A, const float* __restrict__ B,
                  float* __restrict__ C, const float* __restrict__ bias)
{
    constexpr int K = 256;
    constexpr int BM = 128, BN = 128, BK = 16;

    __shared__ float As[BK][BM];   // transposed A tile
    __shared__ float Bs[BK][BN];

    const int tid = threadIdx.x;
    const int tm  = tid >> 4;      // 0..15
    const int tn  = tid & 15;      // 0..15

    const size_t rowbase = (size_t)blockIdx.y * BM;
    const int    colbase = blockIdx.x * BN;

    unsigned long long acc[8][4];
#pragma unroll
    for (int i = 0; i < 8; i++)
#pragma unroll
        for (int j = 0; j < 4; j++) acc[i][j] = 0ull;

    const float* Ag = A + rowbase * K;
    const float* Bg = B + colbase;

    for (int kt = 0; kt < K / BK; kt++) {
        // A tile: 128 rows x 16 k, stored transposed As[k][m]
#pragma unroll
        for (int i = 0; i < 2; i++) {
            int f = tid + i * 256;           // 0..511 float4
            int r = f >> 2;                  // row 0..127
            int c = (f & 3) << 2;            // k 0,4,8,12
            float4 v = *(const float4*)(Ag + (size_t)r * K + kt * BK + c);
            As[c + 0][r] = v.x; As[c + 1][r] = v.y;
            As[c + 2][r] = v.z; As[c + 3][r] = v.w;
        }
        // B tile: 16 k-rows x 128 n
#pragma unroll
        for (int i = 0; i < 2; i++) {
            int f = tid + i * 256;
            int r = f >> 5;                  // k 0..15
            int c = (f & 31) << 2;           // n 0..124
            *(float4*)&Bs[r][c] = *(const float4*)(Bg + (size_t)(kt * BK + r) * N + c);
        }
        __syncthreads();

#pragma unroll
        for (int kk = 0; kk < BK; kk++) {
            float4 a0 = *(const float4*)&As[kk][tm * 8];
            float4 a1 = *(const float4*)&As[kk][tm * 8 + 4];
            ulonglong2 bv0 = *(const ulonglong2*)&Bs[kk][tn * 8];
            ulonglong2 bv1 = *(const ulonglong2*)&Bs[kk][tn * 8 + 4];
            unsigned long long bb[4] = { bv0.x, bv0.y, bv1.x, bv1.y };
            float av[8] = { a0.x, a0.y, a0.z, a0.w, a1.x, a1.y, a1.z, a1.w };
#pragma unroll
            for (int i = 0; i < 8; i++) {
                unsigned long long aa = pack2(av[i], av[i]);
#pragma unroll
                for (int j = 0; j < 4; j++) ffma2(acc[i][j], aa, bb[j]);
            }
        }
        __syncthreads();
    }

    // epilogue
    const size_t crow = rowbase + tm * 8;
    const int    ccol = colbase + tn * 8;
    float4 bb0 = make_float4(0.f, 0.f, 0.f, 0.f);
    float4 bb1 = make_float4(0.f, 0.f, 0.f, 0.f);
    if (bias) {
        bb0 = *(const float4*)(bias + ccol);
        bb1 = *(const float4*)(bias + ccol + 4);
    }
#pragma unroll
    for (int i = 0; i < 8; i++) {
        float4 r0, r1;
        unpack2(acc[i][0], r0.x, r0.y); unpack2(acc[i][1], r0.z, r0.w);
        unpack2(acc[i][2], r1.x, r1.y); unpack2(acc[i][3], r1.z, r1.w);
        r0.x += bb0.x; r0.y += bb0.y; r0.z += bb0.z; r0.w += bb0.w;
        r1.x += bb1.x; r1.y += bb1.y; r1.z += bb1.z; r1.w += bb1.w;
        *(float4*)(C + (crow + i) * N + ccol)     = r0;
        *(float4*)(C + (crow + i) * N + ccol + 4) = r1;
    }
}

// ---------------- Windowed attention -----------------------------------------
// One CTA per 4x4 window; 128 threads = 8 heads x 16 query rows.
// K,V (16 tokens x 512 floats) staged in smem; Q read straight to registers.
__global__ __launch_bounds__(128)
void attn_kernel(const float* __restrict__ qkv,
                 const float* __restrict__ rpb_table,
                 float* __restrict__ ao)
{
    __shared__ float skv [16 * 512];   // [token][ k(256) | v(256) ]
    __shared__ float srpb[49 * 8];

    const int tid = threadIdx.x;
    const int wid = blockIdx.x;
    const int b   = wid >> 12;
    const int tb  = (wid >> 6) & 63;
    const int sb  = wid & 63;
    const int base = b * 65536 + tb * 1024 + sb * 4;   // spatial token row of window origin

    for (int i = tid; i < 392; i += 128) srpb[i] = rpb_table[i];

    // stage K,V: qkv columns [256..768) for 16 tokens
#pragma unroll
    for (int i = 0; i < 16; i++) {
        int f = tid + i * 128;            // 0..2047 float4
        int t = f >> 7;                   // token 0..15
        int c = (f & 127) << 2;           // 0..508
        int row = base + (t >> 2) * 256 + (t & 3);
        *(float4*)&skv[t * 512 + c] =
            *(const float4*)(qkv + (size_t)row * NQKV + 256 + c);
    }

    const int h  = tid >> 4;
    const int qi = tid & 15;
    const int qt = qi >> 2, qs = qi & 3;
    const int qrow = base + qt * 256 + qs;

    float4 qv[8];
    const float4* qp = (const float4*)(qkv + (size_t)qrow * NQKV + h * 32);
#pragma unroll
    for (int u = 0; u < 8; u++) qv[u] = qp[u];

    __syncthreads();

    const float scale = 0.17677669529663687f;   // 32^-0.5
    float sc[16];
#pragma unroll
    for (int j = 0; j < 16; j++) {
        const float4* kp = (const float4*)&skv[j * 512 + h * 32];
        float a = 0.f;
#pragma unroll
        for (int u = 0; u < 8; u++) {
            float4 kv = kp[u];
            a += qv[u].x * kv.x + qv[u].y * kv.y + qv[u].z * kv.z + qv[u].w * kv.w;
        }
        int kt = j >> 2, ks = j & 3;
        int ridx = (qt - kt + 3) * 7 + (qs - ks + 3);
        sc[j] = a * scale + srpb[ridx * 8 + h];
    }

    float m = sc[0];
#pragma unroll
    for (int j = 1; j < 16; j++) m = fmaxf(m, sc[j]);
    float s = 0.f;
#pragma unroll
    for (int j = 0; j < 16; j++) { sc[j] = __expf(sc[j] - m); s += sc[j]; }
    const float inv = 1.f / s;

    float4 o[8];
#pragma unroll
    for (int u = 0; u < 8; u++) o[u] = make_float4(0.f, 0.f, 0.f, 0.f);
#pragma unroll
    for (int j = 0; j < 16; j++) {
        float w = sc[j] * inv;
        const float4* vp = (const float4*)&skv[j * 512 + 256 + h * 32];
#pragma unroll
        for (int u = 0; u < 8; u++) {
            float4 vv = vp[u];
            o[u].x += w * vv.x; o[u].y += w * vv.y;
            o[u].z += w * vv.z; o[u].w += w * vv.w;
        }
    }

    float4* op = (float4*)(ao + (size_t)qrow * D_MODEL + h * 32);
#pragma unroll
    for (int u = 0; u < 8; u++) op[u] = o[u];
}

// ---------------- launch ------------------------------------------------------
extern "C" void kernel_launch(void* const* d_in, const int* in_sizes, int n_in,
                              void* d_out, int out_size)
{
    const float* x      = (const float*)d_in[0];   // (4,256,256,256)
    const float* w_qkv  = (const float*)d_in[1];   // (256,768)
    const float* w_proj = (const float*)d_in[2];   // (256,256)
    const float* b_proj = (const float*)d_in[3];   // (256,)
    const float* rpb    = (const float*)d_in[4];   // (49,8)
    float* out = (float*)d_out;

    float *qkv_ptr, *ao_ptr;
    cudaGetSymbolAddress((void**)&qkv_ptr, g_qkv);
    cudaGetSymbolAddress((void**)&ao_ptr,  g_ao);

    dim3 g1(NQKV / 128, M_TOK / 128);
    sgemm_kernel<NQKV><<<g1, 256>>>(x, w_qkv, qkv_ptr, nullptr);

    attn_kernel<<<NWIN, 128>>>(qkv_ptr, rpb, ao_ptr);

    dim3 g3(D_MODEL / 128, M_TOK / 128);
    sgemm_kernel<D_MODEL><<<g3, 256>>>(ao_ptr, w_proj, out, b_proj);
}

// round 6
// speedup vs baseline: 2.6255x; 2.6255x over previous
#include <cuda_runtime.h>
#include <cstdint>

// FiniteWindowTopologicalAttention — tf32 tensor-core GEMMs + fp32 attention
//   K1: qkv = x @ w_qkv            (tf32 mma.sync, 262144 x 768 x 256)
//   K2: windowed attention          (fp32, 16x16 per head, smem-resident)
//   K3: out = ao @ w_proj + b_proj  (tf32 mma.sync, 262144 x 256 x 256)

#define D_MODEL 256
#define NQKV    768
#define M_TOK   262144          // 4 * 256 * 256
#define NWIN    16384           // 4 * 64 * 64

// scratch (allocation-free rule: __device__ globals)
__device__ float g_qkv[(size_t)M_TOK * NQKV];   // 768 MB
__device__ float g_ao [(size_t)M_TOK * D_MODEL];// 256 MB

// ---------------- tf32 / mma helpers -----------------------------------------
__device__ __forceinline__ uint32_t f2tf(float x) {
    uint32_t r;
    asm("cvt.rna.tf32.f32 %0, %1;" : "=r"(r) : "f"(x));
    return r;
}
__device__ __forceinline__ void mma_tf32(float c[4], const uint32_t a[4],
                                         const uint32_t b[2]) {
    asm volatile(
        "mma.sync.aligned.m16n8k8.row.col.f32.tf32.tf32.f32 "
        "{%0,%1,%2,%3}, {%4,%5,%6,%7}, {%8,%9}, {%0,%1,%2,%3};"
        : "+f"(c[0]), "+f"(c[1]), "+f"(c[2]), "+f"(c[3])
        : "r"(a[0]), "r"(a[1]), "r"(a[2]), "r"(a[3]), "r"(b[0]), "r"(b[1]));
}
__device__ __forceinline__ void cp16(uint32_t dst, const void* src) {
    asm volatile("cp.async.cg.shared.global [%0], [%1], 16;"
                 :: "r"(dst), "l"(src));
}

// ---------------- tf32 GEMM: C[M,N] = A[M,256] * B[256,N] (+bias) ------------
// BM=128, BN=128, BK=32. 256 threads = 8 warps (2 m x 4 n), warp tile 64x32.
// Smem pitches: A 36 floats, B 136 floats -> all fragment LDS conflict-free.
#define XS_F (128 * 36)          // 4608 floats
#define WS_F (32 * 136)          // 4352 floats
#define STAGE_F (XS_F + WS_F)    // 8960 floats
#define GEMM_SMEM_BYTES (2 * STAGE_F * 4)   // 71680 B

__global__ __launch_bounds__(256, 2)
void tf32_gemm_kernel(const float* __restrict__ A, const float* __restrict__ B,
                      float* __restrict__ C, const float* __restrict__ bias,
                      int N)
{
    extern __shared__ float smem[];
    const uint32_t sbase = (uint32_t)__cvta_generic_to_shared(smem);

    const int tid  = threadIdx.x;
    const int warp = tid >> 5, lane = tid & 31;
    const int wm = warp >> 2, wn = warp & 3;       // 2 x 4 warp grid
    const int g  = lane >> 2, t = lane & 3;

    const size_t rowbase = (size_t)blockIdx.y * 128;
    const int    colbase = blockIdx.x * 128;

    float acc[4][4][4];
#pragma unroll
    for (int i = 0; i < 4; i++)
#pragma unroll
        for (int j = 0; j < 4; j++)
#pragma unroll
            for (int r = 0; r < 4; r++) acc[i][j][r] = 0.f;

    // tile copy: A 128x32 (1024 x 16B), B 32x128 (1024 x 16B)
    auto issue_tile = [&](int kt, int buf) {
        uint32_t su = sbase + (uint32_t)(buf * STAGE_F * 4);
#pragma unroll
        for (int i = 0; i < 4; i++) {
            int ch = tid + i * 256;
            int r  = ch >> 3, kg = ch & 7;
            cp16(su + (uint32_t)((r * 36 + kg * 4) * 4),
                 A + (rowbase + r) * 256 + kt * 32 + kg * 4);
        }
#pragma unroll
        for (int i = 0; i < 4; i++) {
            int ch = tid + i * 256;
            int k  = ch >> 5, ng = ch & 31;
            cp16(su + (uint32_t)((XS_F + k * 136 + ng * 4) * 4),
                 B + (size_t)(kt * 32 + k) * N + colbase + ng * 4);
        }
        asm volatile("cp.async.commit_group;");
    };

    issue_tile(0, 0);

    for (int kt = 0; kt < 8; kt++) {
        if (kt < 7) {
            issue_tile(kt + 1, (kt + 1) & 1);
            asm volatile("cp.async.wait_group 1;");
        } else {
            asm volatile("cp.async.wait_group 0;");
        }
        __syncthreads();

        const float* xs = smem + (kt & 1) * STAGE_F;
        const float* ws = xs + XS_F;

#pragma unroll
        for (int k8 = 0; k8 < 4; k8++) {
            const int k0 = k8 * 8;
            uint32_t a[4][4];
#pragma unroll
            for (int i = 0; i < 4; i++) {
                const int r0 = wm * 64 + i * 16;
                a[i][0] = f2tf(xs[(r0 + g)     * 36 + k0 + t]);
                a[i][1] = f2tf(xs[(r0 + g + 8) * 36 + k0 + t]);
                a[i][2] = f2tf(xs[(r0 + g)     * 36 + k0 + t + 4]);
                a[i][3] = f2tf(xs[(r0 + g + 8) * 36 + k0 + t + 4]);
            }
            uint32_t b[4][2];
#pragma unroll
            for (int j = 0; j < 4; j++) {
                const int c0 = wn * 32 + j * 8;
                b[j][0] = f2tf(ws[(k0 + t)     * 136 + c0 + g]);
                b[j][1] = f2tf(ws[(k0 + t + 4) * 136 + c0 + g]);
            }
#pragma unroll
            for (int i = 0; i < 4; i++)
#pragma unroll
                for (int j = 0; j < 4; j++) mma_tf32(acc[i][j], a[i], b[j]);
        }
        __syncthreads();
    }

    // epilogue: c0,c1 -> (m, n..n+1); c2,c3 -> (m+8, n..n+1)
#pragma unroll
    for (int i = 0; i < 4; i++) {
        const size_t m0 = rowbase + wm * 64 + i * 16 + g;
#pragma unroll
        for (int j = 0; j < 4; j++) {
            const int n0 = colbase + wn * 32 + j * 8 + t * 2;
            float2 v0 = make_float2(acc[i][j][0], acc[i][j][1]);
            float2 v1 = make_float2(acc[i][j][2], acc[i][j][3]);
            if (bias) {
                float2 bb = *(const float2*)(bias + n0);
                v0.x += bb.x; v0.y += bb.y;
                v1.x += bb.x; v1.y += bb.y;
            }
            *(float2*)(C + m0 * N + n0)       = v0;
            *(float2*)(C + (m0 + 8) * N + n0) = v1;
        }
    }
}

// ---------------- Windowed attention (unchanged fp32) -------------------------
__global__ __launch_bounds__(128)
void attn_kernel(const float* __restrict__ qkv,
                 const float* __restrict__ rpb_table,
                 float* __restrict__ ao)
{
    __shared__ float skv [16 * 512];   // [token][ k(256) | v(256) ]
    __shared__ float srpb[49 * 8];

    const int tid = threadIdx.x;
    const int wid = blockIdx.x;
    const int b   = wid >> 12;
    const int tb  = (wid >> 6) & 63;
    const int sb  = wid & 63;
    const int base = b * 65536 + tb * 1024 + sb * 4;

    for (int i = tid; i < 392; i += 128) srpb[i] = rpb_table[i];

#pragma unroll
    for (int i = 0; i < 16; i++) {
        int f = tid + i * 128;
        int tok = f >> 7;
        int c = (f & 127) << 2;
        int row = base + (tok >> 2) * 256 + (tok & 3);
        *(float4*)&skv[tok * 512 + c] =
            *(const float4*)(qkv + (size_t)row * NQKV + 256 + c);
    }

    const int h  = tid >> 4;
    const int qi = tid & 15;
    const int qt = qi >> 2, qs = qi & 3;
    const int qrow = base + qt * 256 + qs;

    float4 qv[8];
    const float4* qp = (const float4*)(qkv + (size_t)qrow * NQKV + h * 32);
#pragma unroll
    for (int u = 0; u < 8; u++) qv[u] = qp[u];

    __syncthreads();

    const float scale = 0.17677669529663687f;   // 32^-0.5
    float sc[16];
#pragma unroll
    for (int j = 0; j < 16; j++) {
        const float4* kp = (const float4*)&skv[j * 512 + h * 32];
        float a = 0.f;
#pragma unroll
        for (int u = 0; u < 8; u++) {
            float4 kv = kp[u];
            a += qv[u].x * kv.x + qv[u].y * kv.y + qv[u].z * kv.z + qv[u].w * kv.w;
        }
        int kt = j >> 2, ks = j & 3;
        int ridx = (qt - kt + 3) * 7 + (qs - ks + 3);
        sc[j] = a * scale + srpb[ridx * 8 + h];
    }

    float m = sc[0];
#pragma unroll
    for (int j = 1; j < 16; j++) m = fmaxf(m, sc[j]);
    float s = 0.f;
#pragma unroll
    for (int j = 0; j < 16; j++) { sc[j] = __expf(sc[j] - m); s += sc[j]; }
    const float inv = 1.f / s;

    float4 o[8];
#pragma unroll
    for (int u = 0; u < 8; u++) o[u] = make_float4(0.f, 0.f, 0.f, 0.f);
#pragma unroll
    for (int j = 0; j < 16; j++) {
        float w = sc[j] * inv;
        const float4* vp = (const float4*)&skv[j * 512 + 256 + h * 32];
#pragma unroll
        for (int u = 0; u < 8; u++) {
            float4 vv = vp[u];
            o[u].x += w * vv.x; o[u].y += w * vv.y;
            o[u].z += w * vv.z; o[u].w += w * vv.w;
        }
    }

    float4* op = (float4*)(ao + (size_t)qrow * D_MODEL + h * 32);
#pragma unroll
    for (int u = 0; u < 8; u++) op[u] = o[u];
}

// ---------------- launch ------------------------------------------------------
extern "C" void kernel_launch(void* const* d_in, const int* in_sizes, int n_in,
                              void* d_out, int out_size)
{
    const float* x      = (const float*)d_in[0];   // (4,256,256,256)
    const float* w_qkv  = (const float*)d_in[1];   // (256,768)
    const float* w_proj = (const float*)d_in[2];   // (256,256)
    const float* b_proj = (const float*)d_in[3];   // (256,)
    const float* rpb    = (const float*)d_in[4];   // (49,8)
    float* out = (float*)d_out;

    float *qkv_ptr, *ao_ptr;
    cudaGetSymbolAddress((void**)&qkv_ptr, g_qkv);
    cudaGetSymbolAddress((void**)&ao_ptr,  g_ao);

    cudaFuncSetAttribute(tf32_gemm_kernel,
                         cudaFuncAttributeMaxDynamicSharedMemorySize,
                         GEMM_SMEM_BYTES);

    dim3 g1(NQKV / 128, M_TOK / 128);
    tf32_gemm_kernel<<<g1, 256, GEMM_SMEM_BYTES>>>(x, w_qkv, qkv_ptr,
                                                   nullptr, NQKV);

    attn_kernel<<<NWIN, 128>>>(qkv_ptr, rpb, ao_ptr);

    dim3 g3(D_MODEL / 128, M_TOK / 128);
    tf32_gemm_kernel<<<g3, 256, GEMM_SMEM_BYTES>>>(ao_ptr, w_proj, out,
                                                   b_proj, D_MODEL);
}

// round 10
// speedup vs baseline: 2.7783x; 1.0582x over previous
#include <cuda_runtime.h>
#include <cstdint>

// FiniteWindowTopologicalAttention — tf32 mma.sync GEMMs (pre-rounded operands)
//   K0a: round x -> tf32 copy            (stream, ~85us)
//   K0b: round weights -> tf32 copies    (tiny)
//   K1 : qkv = x @ w_qkv                 (tf32 mma, warp tile 64x64, no cvt)
//   K2 : windowed attention              (fp32; writes tf32-rounded ao)
//   K3 : out = ao @ w_proj + b_proj      (tf32 mma)
//
// NOTE: tcgen05.ld/st/wait are NOT available at this toolchain's ptxas target
// (sm_103 family baseline, not sm_103a) — TMEM accumulators are unreadable, so
// tcgen05 MMA is unusable. mma.sync tf32 is the fastest legal tensor path.

#define D_MODEL 256
#define NQKV    768
#define M_TOK   262144          // 4 * 256 * 256
#define NWIN    16384           // 4 * 64 * 64

// scratch (allocation-free rule: __device__ globals)
__device__ float g_qkv   [(size_t)M_TOK * NQKV];     // 768 MB
__device__ float g_ao    [(size_t)M_TOK * D_MODEL];  // 256 MB (tf32-rounded)
__device__ float g_xtf   [(size_t)M_TOK * D_MODEL];  // 256 MB (tf32-rounded x)
__device__ float g_wqkv_r [D_MODEL * NQKV];          // rounded, same layout
__device__ float g_wproj_r[D_MODEL * D_MODEL];

// ---------------- helpers -----------------------------------------------------
__device__ __forceinline__ float tf32r(float x) {
    uint32_t r;
    asm("cvt.rna.tf32.f32 %0, %1;" : "=r"(r) : "f"(x));
    return __uint_as_float(r);
}
__device__ __forceinline__ void mma_tf32(float c[4], const uint32_t a[4],
                                         const uint32_t b[2]) {
    asm volatile(
        "mma.sync.aligned.m16n8k8.row.col.f32.tf32.tf32.f32 "
        "{%0,%1,%2,%3}, {%4,%5,%6,%7}, {%8,%9}, {%0,%1,%2,%3};"
        : "+f"(c[0]), "+f"(c[1]), "+f"(c[2]), "+f"(c[3])
        : "r"(a[0]), "r"(a[1]), "r"(a[2]), "r"(a[3]), "r"(b[0]), "r"(b[1]));
}
__device__ __forceinline__ void cp16(uint32_t dst, const void* src) {
    asm volatile("cp.async.cg.shared.global [%0], [%1], 16;"
                 :: "r"(dst), "l"(src));
}

// ---------------- pre-pass kernels --------------------------------------------
__global__ void round_x_kernel(const float4* __restrict__ in,
                               float4* __restrict__ out, int n4)
{
    int i = blockIdx.x * blockDim.x + threadIdx.x;
    if (i < n4) {
        float4 v = in[i];
        v.x = tf32r(v.x); v.y = tf32r(v.y); v.z = tf32r(v.z); v.w = tf32r(v.w);
        out[i] = v;
    }
}
__global__ void round_w_kernel(const float* __restrict__ in,
                               float* __restrict__ out, int n)
{
    int i = blockIdx.x * blockDim.x + threadIdx.x;
    if (i < n) out[i] = tf32r(in[i]);
}

// ---------------- tf32 GEMM: C[M,N] = A[M,256] * B[256,N] (+bias) ------------
// BM=128, BN=128, BK=32. 128 threads = 4 warps (2m x 2n), warp tile 64x64.
// All operands pre-rounded to tf32 -> fragment loads are raw uint32, no cvt.
// Smem pitches: A 36 floats, B 136 floats -> fragment LDS conflict-free.
#define XS_F (128 * 36)          // 4608 floats
#define WS_F (32 * 136)          // 4352 floats
#define STAGE_F (XS_F + WS_F)    // 8960 floats
#define GEMM_SMEM_BYTES (2 * STAGE_F * 4)   // 71680 B

__global__ __launch_bounds__(128, 2)
void tf32_gemm_kernel(const float* __restrict__ A, const float* __restrict__ B,
                      float* __restrict__ C, const float* __restrict__ bias,
                      int N)
{
    extern __shared__ float smem[];
    const uint32_t sbase = (uint32_t)__cvta_generic_to_shared(smem);

    const int tid  = threadIdx.x;
    const int warp = tid >> 5, lane = tid & 31;
    const int wm = warp >> 1, wn = warp & 1;       // 2 x 2 warp grid, 64x64 each
    const int g  = lane >> 2, t = lane & 3;

    const size_t rowbase = (size_t)blockIdx.y * 128;
    const int    colbase = blockIdx.x * 128;

    float acc[4][8][4];
#pragma unroll
    for (int i = 0; i < 4; i++)
#pragma unroll
        for (int j = 0; j < 8; j++)
#pragma unroll
            for (int r = 0; r < 4; r++) acc[i][j][r] = 0.f;

    // tile copy: A 128x32 floats (1024 x 16B), B 32x128 (1024 x 16B); 8 each/thr
    auto issue_tile = [&](int kt, int buf) {
        uint32_t su = sbase + (uint32_t)(buf * STAGE_F * 4);
#pragma unroll
        for (int i = 0; i < 8; i++) {
            int ch = tid + i * 128;
            int r  = ch >> 3, kg = ch & 7;
            cp16(su + (uint32_t)((r * 36 + kg * 4) * 4),
                 A + (rowbase + r) * 256 + kt * 32 + kg * 4);
        }
#pragma unroll
        for (int i = 0; i < 8; i++) {
            int ch = tid + i * 128;
            int r  = ch >> 5, c = (ch & 31) << 2;
            cp16(su + (uint32_t)((XS_F + r * 136 + c) * 4),
                 B + (size_t)(kt * 32 + r) * N + colbase + c);
        }
        asm volatile("cp.async.commit_group;");
    };

    issue_tile(0, 0);

    for (int kt = 0; kt < 8; kt++) {
        if (kt < 7) {
            issue_tile(kt + 1, (kt + 1) & 1);
            asm volatile("cp.async.wait_group 1;");
        } else {
            asm volatile("cp.async.wait_group 0;");
        }
        __syncthreads();

        const uint32_t* xs = (const uint32_t*)(smem + (kt & 1) * STAGE_F);
        const uint32_t* ws = xs + XS_F;

#pragma unroll
        for (int k8 = 0; k8 < 4; k8++) {
            const int k0 = k8 * 8;
            uint32_t a[4][4];
#pragma unroll
            for (int i = 0; i < 4; i++) {
                const int r0 = wm * 64 + i * 16;
                a[i][0] = xs[(r0 + g)     * 36 + k0 + t];
                a[i][1] = xs[(r0 + g + 8) * 36 + k0 + t];
                a[i][2] = xs[(r0 + g)     * 36 + k0 + t + 4];
                a[i][3] = xs[(r0 + g + 8) * 36 + k0 + t + 4];
            }
            uint32_t b[8][2];
#pragma unroll
            for (int j = 0; j < 8; j++) {
                const int c0 = wn * 64 + j * 8;
                b[j][0] = ws[(k0 + t)     * 136 + c0 + g];
                b[j][1] = ws[(k0 + t + 4) * 136 + c0 + g];
            }
#pragma unroll
            for (int i = 0; i < 4; i++)
#pragma unroll
                for (int j = 0; j < 8; j++) mma_tf32(acc[i][j], a[i], b[j]);
        }
        __syncthreads();
    }

    // epilogue: c0,c1 -> (m, n..n+1); c2,c3 -> (m+8, n..n+1)
#pragma unroll
    for (int i = 0; i < 4; i++) {
        const size_t m0 = rowbase + wm * 64 + i * 16 + g;
#pragma unroll
        for (int j = 0; j < 8; j++) {
            const int n0 = colbase + wn * 64 + j * 8 + t * 2;
            float2 v0 = make_float2(acc[i][j][0], acc[i][j][1]);
            float2 v1 = make_float2(acc[i][j][2], acc[i][j][3]);
            if (bias) {
                float2 bb = *(const float2*)(bias + n0);
                v0.x += bb.x; v0.y += bb.y;
                v1.x += bb.x; v1.y += bb.y;
            }
            *(float2*)(C + m0 * N + n0)       = v0;
            *(float2*)(C + (m0 + 8) * N + n0) = v1;
        }
    }
}

// ---------------- Windowed attention (fp32; writes tf32-rounded ao) ----------
__global__ __launch_bounds__(128)
void attn_kernel(const float* __restrict__ qkv,
                 const float* __restrict__ rpb_table,
                 float* __restrict__ ao)
{
    __shared__ float skv [16 * 512];   // [token][ k(256) | v(256) ]
    __shared__ float srpb[49 * 8];

    const int tid = threadIdx.x;
    const int wid = blockIdx.x;
    const int b   = wid >> 12;
    const int tb  = (wid >> 6) & 63;
    const int sb_ = wid & 63;
    const int base = b * 65536 + tb * 1024 + sb_ * 4;

    for (int i = tid; i < 392; i += 128) srpb[i] = rpb_table[i];

#pragma unroll
    for (int i = 0; i < 16; i++) {
        int f = tid + i * 128;
        int tok = f >> 7;
        int c = (f & 127) << 2;
        int row = base + (tok >> 2) * 256 + (tok & 3);
        *(float4*)&skv[tok * 512 + c] =
            *(const float4*)(qkv + (size_t)row * NQKV + 256 + c);
    }

    const int h  = tid >> 4;
    const int qi = tid & 15;
    const int qt = qi >> 2, qs = qi & 3;
    const int qrow = base + qt * 256 + qs;

    float4 qv[8];
    const float4* qp = (const float4*)(qkv + (size_t)qrow * NQKV + h * 32);
#pragma unroll
    for (int u = 0; u < 8; u++) qv[u] = qp[u];

    __syncthreads();

    const float scale = 0.17677669529663687f;   // 32^-0.5
    float sc[16];
#pragma unroll
    for (int j = 0; j < 16; j++) {
        const float4* kp = (const float4*)&skv[j * 512 + h * 32];
        float a = 0.f;
#pragma unroll
        for (int u = 0; u < 8; u++) {
            float4 kv = kp[u];
            a += qv[u].x * kv.x + qv[u].y * kv.y + qv[u].z * kv.z + qv[u].w * kv.w;
        }
        int kt = j >> 2, ks = j & 3;
        int ridx = (qt - kt + 3) * 7 + (qs - ks + 3);
        sc[j] = a * scale + srpb[ridx * 8 + h];
    }

    float m = sc[0];
#pragma unroll
    for (int j = 1; j < 16; j++) m = fmaxf(m, sc[j]);
    float s = 0.f;
#pragma unroll
    for (int j = 0; j < 16; j++) { sc[j] = __expf(sc[j] - m); s += sc[j]; }
    const float inv = 1.f / s;

    float4 o[8];
#pragma unroll
    for (int u = 0; u < 8; u++) o[u] = make_float4(0.f, 0.f, 0.f, 0.f);
#pragma unroll
    for (int j = 0; j < 16; j++) {
        float w = sc[j] * inv;
        const float4* vp = (const float4*)&skv[j * 512 + 256 + h * 32];
#pragma unroll
        for (int u = 0; u < 8; u++) {
            float4 vv = vp[u];
            o[u].x += w * vv.x; o[u].y += w * vv.y;
            o[u].z += w * vv.z; o[u].w += w * vv.w;
        }
    }

    // write tf32-rounded ao so K3 fragment loads need no cvt
    float4* op = (float4*)(ao + (size_t)qrow * D_MODEL + h * 32);
#pragma unroll
    for (int u = 0; u < 8; u++) {
        float4 v = o[u];
        v.x = tf32r(v.x); v.y = tf32r(v.y); v.z = tf32r(v.z); v.w = tf32r(v.w);
        op[u] = v;
    }
}

// ---------------- launch ------------------------------------------------------
extern "C" void kernel_launch(void* const* d_in, const int* in_sizes, int n_in,
                              void* d_out, int out_size)
{
    const float* x      = (const float*)d_in[0];   // (4,256,256,256)
    const float* w_qkv  = (const float*)d_in[1];   // (256,768)
    const float* w_proj = (const float*)d_in[2];   // (256,256)
    const float* b_proj = (const float*)d_in[3];   // (256,)
    const float* rpb    = (const float*)d_in[4];   // (49,8)
    float* out = (float*)d_out;

    float *qkv_p, *ao_p, *xtf_p, *wq_p, *wp_p;
    cudaGetSymbolAddress((void**)&qkv_p, g_qkv);
    cudaGetSymbolAddress((void**)&ao_p,  g_ao);
    cudaGetSymbolAddress((void**)&xtf_p, g_xtf);
    cudaGetSymbolAddress((void**)&wq_p,  g_wqkv_r);
    cudaGetSymbolAddress((void**)&wp_p,  g_wproj_r);

    cudaFuncSetAttribute(tf32_gemm_kernel,
                         cudaFuncAttributeMaxDynamicSharedMemorySize,
                         GEMM_SMEM_BYTES);

    // pre-round GEMM operands to tf32 (bit-identical numerics to per-fragment
    // cvt.rna, done once per element instead of per use)
    const int n4 = (M_TOK * D_MODEL) / 4;
    round_x_kernel<<<n4 / 256, 256>>>((const float4*)x, (float4*)xtf_p, n4);
    round_w_kernel<<<(D_MODEL * NQKV) / 256, 256>>>(w_qkv, wq_p, D_MODEL * NQKV);
    round_w_kernel<<<(D_MODEL * D_MODEL) / 256, 256>>>(w_proj, wp_p,
                                                       D_MODEL * D_MODEL);

    // K1: qkv = x @ w_qkv
    tf32_gemm_kernel<<<dim3(NQKV / 128, M_TOK / 128), 128, GEMM_SMEM_BYTES>>>(
        xtf_p, wq_p, qkv_p, nullptr, NQKV);

    // K2: attention
    attn_kernel<<<NWIN, 128>>>(qkv_p, rpb, ao_p);

    // K3: out = ao @ w_proj + b_proj
    tf32_gemm_kernel<<<dim3(D_MODEL / 128, M_TOK / 128), 128, GEMM_SMEM_BYTES>>>(
        ao_p, wp_p, out, b_proj, D_MODEL);
}